// round 5
// baseline (speedup 1.0000x reference)
#include <cuda_runtime.h>
#include <math.h>

typedef unsigned long long ull;

// ---------------- problem constants ----------------
#define NNODE 200
#define IMGF  2048
#define HD1   512
#define HD2   256
#define NCH   1024
#define NEDGE 39800
#define TE    32

// ---------------- f32x2 helpers ----------------
__device__ __forceinline__ ull pack2(float a) {
    ull r; asm("mov.b64 %0,{%1,%1};" : "=l"(r) : "f"(a)); return r;
}
__device__ __forceinline__ void ffma2(ull& acc, ull a, ull b) {
    asm("fma.rn.f32x2 %0,%1,%2,%0;" : "+l"(acc) : "l"(a), "l"(b));
}
__device__ __forceinline__ float2 unpk(ull v) {
    float2 r; asm("mov.b64 {%0,%1},%2;" : "=f"(r.x), "=f"(r.y) : "l"(v)); return r;
}

// ---------------- device scratch ----------------
#define OFF_H1   0
#define OFF_H2   (OFF_H1 + NNODE*HD1)
#define OFF_M    (OFF_H2 + NNODE*HD2)
#define OFF_W3M  (OFF_M  + NNODE*512)
#define ZERO_CNT (OFF_W3M + HD2*512)           // h1,h2,M,W3M zeroed
#define OFF_WT   (ZERO_CNT)
#define OFF_P    (OFF_WT + NCH*512)
#define OFF_Q    (OFF_P + NNODE*256)
#define OFF_GC   (OFF_Q + NNODE*256)           // Gc[12][256]
#define OFF_BASE (OFF_GC + 12*256)
#define OFF_BM   (OFF_BASE + 16)
#define OFF_CV   (OFF_BM + 512)
#define SCR_TOTAL (OFF_CV + NNODE*4)
__device__ float g_scr[SCR_TOTAL];

// wt[i][k*4+o] = wp2[k][i*4+o] : float4-granular transpose
__global__ void k_tr(const float* __restrict__ wp2, float* __restrict__ wt) {
    int t = blockIdx.x * 256 + threadIdx.x;
    if (t >= 128 * 1024) return;
    int k = t >> 10, i = t & 1023;
    float4 v = ((const float4*)wp2)[t];
    ((float4*)wt)[i * 128 + k] = v;
}

// bM[j] = sum_i b3[i] * wt[i*512+j]
__global__ void k_bm(const float* __restrict__ b3, const float* __restrict__ wt,
                     float* __restrict__ bm) {
    int j = blockIdx.x * 128 + threadIdx.x;
    float s = 0.f;
    #pragma unroll 8
    for (int i = 0; i < NCH; ++i) s += b3[i] * wt[i * 512 + j];
    bm[j] = s;
}

// Wcat[i][c]: c<4 -> wi[i*4+c] ; c<8 -> bp2[i*4+c-4] ; else rw[i*4+c-8]
__device__ __forceinline__ float wcat(const float* wi, const float* bp2,
                                      const float* rw, int i, int c) {
    if (c < 4) return wi[i * 4 + c];
    if (c < 8) return bp2[i * 4 + c - 4];
    return rw[i * 4 + c - 8];
}

// Gc[c][i2] = sum_i w3[i2][i] * Wcat[i][c]   (8 blocks x 384 thr, smem tiled)
__global__ void __launch_bounds__(384) k_g(
    const float* __restrict__ w3, const float* __restrict__ wi,
    const float* __restrict__ bp2, const float* __restrict__ rw,
    float* __restrict__ Gc) {
    __shared__ float sW3[32 * 65];
    __shared__ float sWc[64][12];
    const int t = threadIdx.x, b = blockIdx.x;
    const int i2l = t / 12, c = t - i2l * 12;
    float acc = 0.f;
    for (int i0 = 0; i0 < NCH; i0 += 64) {
        for (int m = t; m < 32 * 64; m += 384) {
            int row = m >> 6, col = m & 63;
            sW3[row * 65 + col] = w3[(size_t)(b * 32 + row) * NCH + i0 + col];
        }
        // FIX: full 64x12 tile (768 entries) staged by 384 threads -> loop
        for (int m = t; m < 64 * 12; m += 384) {
            int row = m / 12, cc = m - row * 12;
            sWc[row][cc] = wcat(wi, bp2, rw, i0 + row, cc);
        }
        __syncthreads();
        if (i2l < 32) {
            #pragma unroll 16
            for (int ii = 0; ii < 64; ++ii)
                acc += sW3[i2l * 65 + ii] * sWc[ii][c];
        }
        __syncthreads();
    }
    if (i2l < 32) Gc[c * 256 + b * 32 + i2l] = acc;
}

// base[c] = sum_i b3[i] * Wcat[i][c]
__global__ void __launch_bounds__(384) k_base(
    const float* __restrict__ b3, const float* __restrict__ wi,
    const float* __restrict__ bp2, const float* __restrict__ rw,
    float* __restrict__ base) {
    __shared__ float sred[32][13];
    int t = threadIdx.x;
    int seg = t / 12, c = t - seg * 12;
    float s = 0.f;
    #pragma unroll
    for (int k = 0; k < 32; ++k) {
        int i = seg * 32 + k;
        s += b3[i] * wcat(wi, bp2, rw, i, c);
    }
    sred[seg][c] = s;
    __syncthreads();
    if (t < 12) {
        float v = 0.f;
        #pragma unroll
        for (int g = 0; g < 32; ++g) v += sred[g][t];
        base[t] = v;
    }
}

// P[n][j] = attr(n) @ we1[0:8]  ;  Q[n][j] = attr(n) @ we1[8:16]
__global__ void k_pq(const float* __restrict__ bbox, const float* __restrict__ dirs,
                     const float* __restrict__ we1,
                     float* __restrict__ P, float* __restrict__ Q) {
    __shared__ float a[8];
    int n = blockIdx.y, j = blockIdx.x * 128 + threadIdx.x;
    if (threadIdx.x < 8) {
        int c = threadIdx.x;
        a[c] = (c < 4) ? bbox[n * 4 + c] * (1.0f / 1024.0f) : dirs[n * 4 + c - 4];
    }
    __syncthreads();
    float p = 0.f, q = 0.f;
    #pragma unroll
    for (int c = 0; c < 8; ++c) {
        p += a[c] * we1[c * 256 + j];
        q += a[c] * we1[(c + 8) * 256 + j];
    }
    P[n * 256 + j] = p;
    Q[n * 256 + j] = q;
}

// vec from h2: 12 per-node values
__global__ void __launch_bounds__(256) k_vec(
    const float* __restrict__ h2, const float* __restrict__ Gc,
    const float* __restrict__ base,
    const float* __restrict__ bi, const float* __restrict__ rb,
    float* __restrict__ out_expl, float* __restrict__ cvec,
    float* __restrict__ out_agg) {
    int n = blockIdx.x, t = threadIdx.x;
    float xv = fmaxf(h2[(size_t)n * HD2 + t], 0.f);
    float v[12];
    #pragma unroll
    for (int c = 0; c < 12; ++c) v[c] = xv * Gc[c * 256 + t];
    #pragma unroll
    for (int s = 16; s; s >>= 1)
        #pragma unroll
        for (int c = 0; c < 12; ++c) v[c] += __shfl_xor_sync(0xffffffffu, v[c], s);
    __shared__ float red[8][13];
    if ((t & 31) == 0)
        #pragma unroll
        for (int c = 0; c < 12; ++c) red[t >> 5][c] = v[c];
    __syncthreads();
    if (t < 12) {
        float s = base[t];
        #pragma unroll
        for (int w = 0; w < 8; ++w) s += red[w][t];
        int o = t & 3;
        if (t < 4)       out_expl[n * 4 + o] = 1.f / (1.f + __expf(-(s + bi[o])));
        else if (t < 8)  cvec[n * 4 + o] = s;
        else             out_agg[n * 4 + o] = s + rb[o];
    }
}

// ---------------- split-K SGEMM: atomicAdd(C, A@B), split 0 adds bias --------
template <int RELU_A>
__global__ void __launch_bounds__(256) sgemm_sk(
    const float* __restrict__ A, const float* __restrict__ B,
    const float* __restrict__ bias, float* __restrict__ C,
    int M, int N, int K, int Ks) {
    __shared__ float sA[16][36];
    __shared__ float sB[16][132];
    const int tid = threadIdx.x;
    const int tx = tid & 31, ty = tid >> 5;
    const int m0 = blockIdx.y * 32, n0 = blockIdx.x * 128;
    const int kbeg = blockIdx.z * Ks;
    ull acc[8];
    #pragma unroll
    for (int i = 0; i < 8; ++i) acc[i] = 0ULL;

    for (int k0 = kbeg; k0 < kbeg + Ks; k0 += 16) {
        {
            int m = tid >> 3, kq = (tid & 7) * 2;
            float2 a = make_float2(0.f, 0.f);
            if (m0 + m < M) a = *(const float2*)(A + (size_t)(m0 + m) * K + k0 + kq);
            if (RELU_A) { a.x = fmaxf(a.x, 0.f); a.y = fmaxf(a.y, 0.f); }
            sA[kq][m] = a.x; sA[kq + 1][m] = a.y;
        }
        {
            int k = tid >> 4, n8 = (tid & 15) * 8;
            const float* bp = B + (size_t)(k0 + k) * N + n0 + n8;
            float4 b0 = *(const float4*)(bp);
            float4 b1 = *(const float4*)(bp + 4);
            *(float4*)&sB[k][n8] = b0;
            *(float4*)&sB[k][n8 + 4] = b1;
        }
        __syncthreads();
        #pragma unroll
        for (int k = 0; k < 16; ++k) {
            float4 av = *(const float4*)&sA[k][ty * 4];
            ulonglong2 bv = *(const ulonglong2*)&sB[k][tx * 4];
            ull a0 = pack2(av.x), a1 = pack2(av.y), a2 = pack2(av.z), a3 = pack2(av.w);
            ffma2(acc[0], a0, bv.x); ffma2(acc[1], a0, bv.y);
            ffma2(acc[2], a1, bv.x); ffma2(acc[3], a1, bv.y);
            ffma2(acc[4], a2, bv.x); ffma2(acc[5], a2, bv.y);
            ffma2(acc[6], a3, bv.x); ffma2(acc[7], a3, bv.y);
        }
        __syncthreads();
    }
    const bool addb = (bias != nullptr) && (blockIdx.z == 0);
    #pragma unroll
    for (int r = 0; r < 4; ++r) {
        int row = m0 + ty * 4 + r;
        if (row >= M) continue;
        float2 v01 = unpk(acc[r * 2]), v23 = unpk(acc[r * 2 + 1]);
        float v[4] = {v01.x, v01.y, v23.x, v23.y};
        int col = n0 + tx * 4;
        #pragma unroll
        for (int j = 0; j < 4; ++j) {
            float o = v[j];
            if (addb) o += bias[col + j];
            atomicAdd(&C[(size_t)row * N + col + j], o);
        }
    }
}

// ---------------- edge MLP (phases 1-3 only) ----------------
__global__ void __launch_bounds__(128) k_edge_mlp(
    const float* __restrict__ P, const float* __restrict__ Q,
    const float* __restrict__ pri,
    const float* __restrict__ be1,
    const float* __restrict__ we2, const float* __restrict__ be2,
    const float* __restrict__ we3, const float* __restrict__ be3,
    float* __restrict__ out_ea) {
    __shared__ float s_big[TE * 264];
    __shared__ float s_h2[TE][68];
    __shared__ float s_ea[TE][4];
    __shared__ int s_src[TE], s_dst[TE];

    const int t = threadIdx.x;
    const int e0 = blockIdx.x * TE;

    if (t < TE) {
        int e = e0 + t;
        if (e >= NEDGE) e = NEDGE - 1;
        int i = e / 199;
        int r = e - i * 199;
        int j = (r < i) ? r : (r + 1);
        s_src[t] = i; s_dst[t] = j;
    }
    __syncthreads();

    // phase 1: h1 = relu(P[src] + Q[dst] + be1)
    #pragma unroll
    for (int l = 0; l < 16; ++l) {
        int idx = l * 128 + t;
        int el = idx >> 6, j4 = idx & 63;
        float4 p = ((const float4*)(P + s_src[el] * 256))[j4];
        float4 q = ((const float4*)(Q + s_dst[el] * 256))[j4];
        float4 b = ((const float4*)be1)[j4];
        float4 o;
        o.x = fmaxf(p.x + q.x + b.x, 0.f);
        o.y = fmaxf(p.y + q.y + b.y, 0.f);
        o.z = fmaxf(p.z + q.z + b.z, 0.f);
        o.w = fmaxf(p.w + q.w + b.w, 0.f);
        *(float4*)&s_big[el * 264 + j4 * 4] = o;
    }
    __syncthreads();

    const int eg = t >> 4, cg = t & 15;

    // phase 2: L2 256->64 (f32x2), 2 k's per step
    {
        ull acc01[4], acc23[4];
        #pragma unroll
        for (int e = 0; e < 4; ++e) { acc01[e] = 0ULL; acc23[e] = 0ULL; }
        #pragma unroll 4
        for (int k = 0; k < 256; k += 2) {
            float2 a0 = *(const float2*)&s_big[(eg * 4 + 0) * 264 + k];
            float2 a1 = *(const float2*)&s_big[(eg * 4 + 1) * 264 + k];
            float2 a2 = *(const float2*)&s_big[(eg * 4 + 2) * 264 + k];
            float2 a3 = *(const float2*)&s_big[(eg * 4 + 3) * 264 + k];
            ulonglong2 b0 = *(const ulonglong2*)(we2 + (k + 0) * 64 + cg * 4);
            ulonglong2 b1 = *(const ulonglong2*)(we2 + (k + 1) * 64 + cg * 4);
            ull p;
            p = pack2(a0.x); ffma2(acc01[0], p, b0.x); ffma2(acc23[0], p, b0.y);
            p = pack2(a1.x); ffma2(acc01[1], p, b0.x); ffma2(acc23[1], p, b0.y);
            p = pack2(a2.x); ffma2(acc01[2], p, b0.x); ffma2(acc23[2], p, b0.y);
            p = pack2(a3.x); ffma2(acc01[3], p, b0.x); ffma2(acc23[3], p, b0.y);
            p = pack2(a0.y); ffma2(acc01[0], p, b1.x); ffma2(acc23[0], p, b1.y);
            p = pack2(a1.y); ffma2(acc01[1], p, b1.x); ffma2(acc23[1], p, b1.y);
            p = pack2(a2.y); ffma2(acc01[2], p, b1.x); ffma2(acc23[2], p, b1.y);
            p = pack2(a3.y); ffma2(acc01[3], p, b1.x); ffma2(acc23[3], p, b1.y);
        }
        #pragma unroll
        for (int e = 0; e < 4; ++e) {
            float2 u0 = unpk(acc01[e]), u1 = unpk(acc23[e]);
            s_h2[eg * 4 + e][cg * 4 + 0] = fmaxf(u0.x + be2[cg * 4 + 0], 0.f);
            s_h2[eg * 4 + e][cg * 4 + 1] = fmaxf(u0.y + be2[cg * 4 + 1], 0.f);
            s_h2[eg * 4 + e][cg * 4 + 2] = fmaxf(u1.x + be2[cg * 4 + 2], 0.f);
            s_h2[eg * 4 + e][cg * 4 + 3] = fmaxf(u1.y + be2[cg * 4 + 3], 0.f);
        }
    }
    __syncthreads();

    // phase 3: L3 64->3 + sigmoid + priority bit
    if (t < 96) {
        int e = t / 3, c = t - (t / 3) * 3;
        float s = be3[c];
        #pragma unroll 8
        for (int k = 0; k < 64; ++k) s += s_h2[e][k] * we3[k * 3 + c];
        s_ea[e][c] = 1.f / (1.f + __expf(-s));
    }
    if (t < TE) s_ea[t][3] = (pri[s_src[t]] > pri[s_dst[t]]) ? 1.f : 0.f;
    __syncthreads();

    {
        int e = t >> 2, c = t & 3;
        if (e0 + e < NEDGE) out_ea[(size_t)(e0 + e) * 4 + c] = s_ea[e][c];
    }
}

// ---------------- message kernel: one block per src node ----------------
__global__ void __launch_bounds__(256) k_msg(
    const float* __restrict__ ea, const float* __restrict__ Mn,
    const float* __restrict__ cvec,
    const float* __restrict__ wp1, const float* __restrict__ bp1,
    float* __restrict__ out_agg) {
    __shared__ float sM[512];
    __shared__ float swp[512];
    __shared__ float sbp[128];
    const int src = blockIdx.x, t = threadIdx.x;
    sM[t] = Mn[src * 512 + t];
    sM[t + 256] = Mn[src * 512 + 256 + t];
    swp[t] = wp1[t]; swp[t + 256] = wp1[t + 256];
    if (t < 128) sbp[t] = bp1[t];
    __syncthreads();

    float4 cv = *(const float4*)(cvec + src * 4);
    const int slot = t >> 2, q = t & 3;
    for (int eb = 0; eb < 4; ++eb) {
        int el = eb * 64 + slot;
        if (el >= 199) break;
        int dst = el + (el >= src ? 1 : 0);
        int e = src * 199 + el;
        float4 eav = ((const float4*)ea)[e];
        float4 a = make_float4(0.f, 0.f, 0.f, 0.f);
        #pragma unroll 8
        for (int kk = 0; kk < 32; ++kk) {
            int k = kk * 4 + q;
            float h = sbp[k] + eav.x * swp[k] + eav.y * swp[128 + k]
                             + eav.z * swp[256 + k] + eav.w * swp[384 + k];
            h = fmaxf(h, 0.f);
            float4 m = ((const float4*)sM)[k];
            a.x += h * m.x; a.y += h * m.y; a.z += h * m.z; a.w += h * m.w;
        }
        #pragma unroll
        for (int s = 1; s < 4; s <<= 1) {
            a.x += __shfl_xor_sync(0xffffffffu, a.x, s);
            a.y += __shfl_xor_sync(0xffffffffu, a.y, s);
            a.z += __shfl_xor_sync(0xffffffffu, a.z, s);
            a.w += __shfl_xor_sync(0xffffffffu, a.w, s);
        }
        if (q == 0) {
            atomicAdd(&out_agg[dst * 4 + 0], a.x + cv.x);
            atomicAdd(&out_agg[dst * 4 + 1], a.y + cv.y);
            atomicAdd(&out_agg[dst * 4 + 2], a.z + cv.z);
            atomicAdd(&out_agg[dst * 4 + 3], a.w + cv.w);
        }
    }
}

// ---------------- launch ----------------
extern "C" void kernel_launch(void* const* d_in, const int* in_sizes, int n_in,
                              void* d_out, int out_size) {
    const float* roi  = (const float*)d_in[0];
    const float* bbox = (const float*)d_in[1];
    const float* dir  = (const float*)d_in[2];
    const float* pri  = (const float*)d_in[3];
    const float* w1  = (const float*)d_in[4];  const float* b1  = (const float*)d_in[5];
    const float* w2  = (const float*)d_in[6];  const float* b2  = (const float*)d_in[7];
    const float* w3  = (const float*)d_in[8];  const float* b3  = (const float*)d_in[9];
    const float* wi  = (const float*)d_in[10]; const float* bi  = (const float*)d_in[11];
    const float* we1 = (const float*)d_in[12]; const float* be1 = (const float*)d_in[13];
    const float* we2 = (const float*)d_in[14]; const float* be2 = (const float*)d_in[15];
    const float* we3 = (const float*)d_in[16]; const float* be3 = (const float*)d_in[17];
    const float* wp1 = (const float*)d_in[18]; const float* bp1 = (const float*)d_in[19];
    const float* wp2 = (const float*)d_in[20]; const float* bp2 = (const float*)d_in[21];
    const float* rw  = (const float*)d_in[22]; const float* rb  = (const float*)d_in[23];
    float* out = (float*)d_out;

    float* scr;
    cudaGetSymbolAddress((void**)&scr, g_scr);
    float* p_h1  = scr + OFF_H1;
    float* p_h2  = scr + OFF_H2;
    float* p_M   = scr + OFF_M;
    float* p_w3m = scr + OFF_W3M;
    float* p_wt  = scr + OFF_WT;
    float* p_P   = scr + OFF_P;
    float* p_Q   = scr + OFF_Q;
    float* p_gc  = scr + OFF_GC;
    float* p_bs  = scr + OFF_BASE;
    float* p_bm  = scr + OFF_BM;
    float* p_cv  = scr + OFF_CV;

    static cudaStream_t s1 = nullptr, s2 = nullptr;
    static cudaEvent_t evR = nullptr, ev1 = nullptr, ev2 = nullptr;
    if (!s1) {
        cudaStreamCreateWithFlags(&s1, cudaStreamNonBlocking);
        cudaStreamCreateWithFlags(&s2, cudaStreamNonBlocking);
        cudaEventCreateWithFlags(&evR, cudaEventDisableTiming);
        cudaEventCreateWithFlags(&ev1, cudaEventDisableTiming);
        cudaEventCreateWithFlags(&ev2, cudaEventDisableTiming);
    }

    cudaMemsetAsync(scr, 0, ZERO_CNT * sizeof(float), 0);
    cudaEventRecord(evR, 0);
    cudaStreamWaitEvent(s1, evR, 0);
    cudaStreamWaitEvent(s2, evR, 0);

    // --- branch A (stream 0): data chain L1 -> L2
    sgemm_sk<0><<<dim3(4, 7, 16), 256, 0, 0>>>(roi,  w1, b1, p_h1, NNODE, HD1, IMGF, 128);
    sgemm_sk<1><<<dim3(2, 7, 16), 256, 0, 0>>>(p_h1, w2, b2, p_h2, NNODE, HD2, HD1, 32);

    // --- branch B (s1): weight-side precomputes
    k_tr<<<(128 * 1024) / 256, 256, 0, s1>>>(wp2, p_wt);
    sgemm_sk<0><<<dim3(4, 8, 8), 256, 0, s1>>>(w3, p_wt, (const float*)nullptr, p_w3m,
                                               HD2, 512, NCH, 128);
    k_bm<<<4, 128, 0, s1>>>(b3, p_wt, p_bm);
    k_g<<<8, 384, 0, s1>>>(w3, wi, bp2, rw, p_gc);
    k_base<<<1, 384, 0, s1>>>(b3, wi, bp2, rw, p_bs);
    cudaEventRecord(ev1, s1);

    // --- branch C (s2): edge MLP
    k_pq<<<dim3(2, NNODE), 128, 0, s2>>>(bbox, dir, we1, p_P, p_Q);
    k_edge_mlp<<<(NEDGE + TE - 1) / TE, 128, 0, s2>>>(p_P, p_Q, pri, be1,
                                                      we2, be2, we3, be3,
                                                      out + 1600);
    cudaEventRecord(ev2, s2);

    // --- join: M = relu(h2) @ W3M + bM ; vec from h2
    cudaStreamWaitEvent(0, ev1, 0);
    sgemm_sk<1><<<dim3(4, 7, 8), 256, 0, 0>>>(p_h2, p_w3m, p_bm, p_M,
                                              NNODE, 512, HD2, 32);
    k_vec<<<NNODE, 256, 0, 0>>>(p_h2, p_gc, p_bs, bi, rb, out + 800, p_cv, out);

    // --- final: message passing + scatter
    cudaStreamWaitEvent(0, ev2, 0);
    k_msg<<<NNODE, 256, 0, 0>>>(out + 1600, p_M, p_cv, wp1, bp1, out);
}

// round 6
// speedup vs baseline: 1.1821x; 1.1821x over previous
#include <cuda_runtime.h>
#include <math.h>

typedef unsigned long long ull;

// ---------------- problem constants ----------------
#define NNODE 200
#define IMGF  2048
#define HD1   512
#define HD2   256
#define NCH   1024
#define NEDGE 39800
#define TE    32

// ---------------- f32x2 helpers ----------------
__device__ __forceinline__ ull pack2(float a) {
    ull r; asm("mov.b64 %0,{%1,%1};" : "=l"(r) : "f"(a)); return r;
}
__device__ __forceinline__ void ffma2(ull& acc, ull a, ull b) {
    asm("fma.rn.f32x2 %0,%1,%2,%0;" : "+l"(acc) : "l"(a), "l"(b));
}
__device__ __forceinline__ float2 unpk(ull v) {
    float2 r; asm("mov.b64 {%0,%1},%2;" : "=f"(r.x), "=f"(r.y) : "l"(v)); return r;
}

// ---------------- device scratch ----------------
#define OFF_H1   0
#define OFF_H2   (OFF_H1 + NNODE*HD1)          // 102400
#define OFF_X    (OFF_H2 + NNODE*HD2)          // 153600
#define OFF_M    (OFF_X  + NNODE*NCH)          // 358400
#define ZERO_CNT (OFF_M  + NNODE*512)          // 460800 : h1,h2,x,M zeroed
#define OFF_P    (ZERO_CNT)
#define OFF_Q    (OFF_P + NNODE*256)
#define OFF_CV   (OFF_Q + NNODE*256)
#define SCR_TOTAL (OFF_CV + NNODE*4)
__device__ float g_scr[SCR_TOTAL];

// P[n][j] = attr(n) @ we1[0:8]  ;  Q[n][j] = attr(n) @ we1[8:16]
__global__ void k_pq(const float* __restrict__ bbox, const float* __restrict__ dirs,
                     const float* __restrict__ we1,
                     float* __restrict__ P, float* __restrict__ Q) {
    __shared__ float a[8];
    int n = blockIdx.y, j = blockIdx.x * 128 + threadIdx.x;
    if (threadIdx.x < 8) {
        int c = threadIdx.x;
        a[c] = (c < 4) ? bbox[n * 4 + c] * (1.0f / 1024.0f) : dirs[n * 4 + c - 4];
    }
    __syncthreads();
    float p = 0.f, q = 0.f;
    #pragma unroll
    for (int c = 0; c < 8; ++c) {
        p += a[c] * we1[c * 256 + j];
        q += a[c] * we1[(c + 8) * 256 + j];
    }
    P[n * 256 + j] = p;
    Q[n * 256 + j] = q;
}

// per-node [1024] -> 12 outputs: explicit concepts, c-vector, root term
__global__ void __launch_bounds__(256) k_vec4b(
    const float* __restrict__ x,
    const float* __restrict__ wi, const float* __restrict__ bi,
    const float* __restrict__ bp2,
    const float* __restrict__ rw, const float* __restrict__ rb,
    float* __restrict__ out_expl, float* __restrict__ cvec,
    float* __restrict__ out_agg) {
    int n = blockIdx.x, t = threadIdx.x;
    float4 xv = *(const float4*)(x + (size_t)n * NCH + t * 4);
    float xa[4] = {xv.x, xv.y, xv.z, xv.w};
    float v[12];
    #pragma unroll
    for (int c = 0; c < 12; ++c) v[c] = 0.f;
    #pragma unroll
    for (int j = 0; j < 4; ++j) {
        int i = t * 4 + j;
        float xs = xa[j];
        float4 w0 = *(const float4*)(wi  + i * 4);
        float4 w1 = *(const float4*)(bp2 + i * 4);
        float4 w2 = *(const float4*)(rw  + i * 4);
        v[0] += xs * w0.x; v[1] += xs * w0.y; v[2]  += xs * w0.z; v[3]  += xs * w0.w;
        v[4] += xs * w1.x; v[5] += xs * w1.y; v[6]  += xs * w1.z; v[7]  += xs * w1.w;
        v[8] += xs * w2.x; v[9] += xs * w2.y; v[10] += xs * w2.z; v[11] += xs * w2.w;
    }
    #pragma unroll
    for (int s = 16; s; s >>= 1)
        #pragma unroll
        for (int c = 0; c < 12; ++c) v[c] += __shfl_xor_sync(0xffffffffu, v[c], s);
    __shared__ float red[8][13];
    if ((t & 31) == 0)
        #pragma unroll
        for (int c = 0; c < 12; ++c) red[t >> 5][c] = v[c];
    __syncthreads();
    if (t < 12) {
        float s = 0.f;
        #pragma unroll
        for (int w = 0; w < 8; ++w) s += red[w][t];
        int o = t & 3;
        if (t < 4)       out_expl[n * 4 + o] = 1.f / (1.f + __expf(-(s + bi[o])));
        else if (t < 8)  cvec[n * 4 + o] = s;
        else             out_agg[n * 4 + o] = s + rb[o];
    }
}

// ---------------- split-K SGEMM: atomicAdd(C, A@B), split 0 adds bias --------
// TRB=1: B is wp2 [NCH/4? no: [4096-col rows]] accessed transposed:
//   B_t[i][j] = wp2[(j>>2)*4096 + i*4 + (j&3)]  (i = K index, j = N index)
template <int RELU_A, int TRB>
__global__ void __launch_bounds__(256) sgemm_sk(
    const float* __restrict__ A, const float* __restrict__ B,
    const float* __restrict__ bias, float* __restrict__ C,
    int M, int N, int K, int Ks) {
    __shared__ float sA[16][36];
    __shared__ float sB[16][132];
    const int tid = threadIdx.x;
    const int tx = tid & 31, ty = tid >> 5;
    const int m0 = blockIdx.y * 32, n0 = blockIdx.x * 128;
    const int kbeg = blockIdx.z * Ks;
    ull acc[8];
    #pragma unroll
    for (int i = 0; i < 8; ++i) acc[i] = 0ULL;

    for (int k0 = kbeg; k0 < kbeg + Ks; k0 += 16) {
        {
            int m = tid >> 3, kq = (tid & 7) * 2;
            float2 a = make_float2(0.f, 0.f);
            if (m0 + m < M) a = *(const float2*)(A + (size_t)(m0 + m) * K + k0 + kq);
            if (RELU_A) { a.x = fmaxf(a.x, 0.f); a.y = fmaxf(a.y, 0.f); }
            sA[kq][m] = a.x; sA[kq + 1][m] = a.y;
        }
        if (TRB == 0) {
            int k = tid >> 4, n8 = (tid & 15) * 8;
            const float* bp = B + (size_t)(k0 + k) * N + n0 + n8;
            float4 b0 = *(const float4*)(bp);
            float4 b1 = *(const float4*)(bp + 4);
            *(float4*)&sB[k][n8] = b0;
            *(float4*)&sB[k][n8 + 4] = b1;
        } else {
            // thread -> (k = tid&15, n8 = (tid>>4)*8): 16 consecutive threads
            // read contiguous 256B runs of wp2.
            int k = tid & 15, n8 = (tid >> 4) * 8;
            int i = k0 + k, j0 = n0 + n8;
            const float* bp = B + (size_t)(j0 >> 2) * 4096 + i * 4;
            float4 b0 = *(const float4*)(bp);
            float4 b1 = *(const float4*)(bp + 4096);
            *(float4*)&sB[k][n8] = b0;
            *(float4*)&sB[k][n8 + 4] = b1;
        }
        __syncthreads();
        #pragma unroll
        for (int k = 0; k < 16; ++k) {
            float4 av = *(const float4*)&sA[k][ty * 4];
            ulonglong2 bv = *(const ulonglong2*)&sB[k][tx * 4];
            ull a0 = pack2(av.x), a1 = pack2(av.y), a2 = pack2(av.z), a3 = pack2(av.w);
            ffma2(acc[0], a0, bv.x); ffma2(acc[1], a0, bv.y);
            ffma2(acc[2], a1, bv.x); ffma2(acc[3], a1, bv.y);
            ffma2(acc[4], a2, bv.x); ffma2(acc[5], a2, bv.y);
            ffma2(acc[6], a3, bv.x); ffma2(acc[7], a3, bv.y);
        }
        __syncthreads();
    }
    const bool addb = (bias != nullptr) && (blockIdx.z == 0);
    #pragma unroll
    for (int r = 0; r < 4; ++r) {
        int row = m0 + ty * 4 + r;
        if (row >= M) continue;
        float2 v01 = unpk(acc[r * 2]), v23 = unpk(acc[r * 2 + 1]);
        float v[4] = {v01.x, v01.y, v23.x, v23.y};
        int col = n0 + tx * 4;
        #pragma unroll
        for (int j = 0; j < 4; ++j) {
            float o = v[j];
            if (addb) o += bias[col + j];
            atomicAdd(&C[(size_t)row * N + col + j], o);
        }
    }
}

// ---------------- edge MLP (L1 gather-add, L2, L3) ----------------
__global__ void __launch_bounds__(128) k_edge_mlp(
    const float* __restrict__ P, const float* __restrict__ Q,
    const float* __restrict__ pri,
    const float* __restrict__ be1,
    const float* __restrict__ we2, const float* __restrict__ be2,
    const float* __restrict__ we3, const float* __restrict__ be3,
    float* __restrict__ out_ea) {
    __shared__ float s_big[TE * 264];
    __shared__ float s_h2[TE][68];
    __shared__ float s_ea[TE][4];
    __shared__ int s_src[TE], s_dst[TE];

    const int t = threadIdx.x;
    const int e0 = blockIdx.x * TE;

    if (t < TE) {
        int e = e0 + t;
        if (e >= NEDGE) e = NEDGE - 1;
        int i = e / 199;
        int r = e - i * 199;
        int j = (r < i) ? r : (r + 1);
        s_src[t] = i; s_dst[t] = j;
    }
    __syncthreads();

    // phase 1: h1 = relu(P[src] + Q[dst] + be1)
    #pragma unroll
    for (int l = 0; l < 16; ++l) {
        int idx = l * 128 + t;
        int el = idx >> 6, j4 = idx & 63;
        float4 p = ((const float4*)(P + s_src[el] * 256))[j4];
        float4 q = ((const float4*)(Q + s_dst[el] * 256))[j4];
        float4 b = ((const float4*)be1)[j4];
        float4 o;
        o.x = fmaxf(p.x + q.x + b.x, 0.f);
        o.y = fmaxf(p.y + q.y + b.y, 0.f);
        o.z = fmaxf(p.z + q.z + b.z, 0.f);
        o.w = fmaxf(p.w + q.w + b.w, 0.f);
        *(float4*)&s_big[el * 264 + j4 * 4] = o;
    }
    __syncthreads();

    const int eg = t >> 4, cg = t & 15;

    // phase 2: L2 256->64 (f32x2), 2 k's per step
    {
        ull acc01[4], acc23[4];
        #pragma unroll
        for (int e = 0; e < 4; ++e) { acc01[e] = 0ULL; acc23[e] = 0ULL; }
        #pragma unroll 4
        for (int k = 0; k < 256; k += 2) {
            float2 a0 = *(const float2*)&s_big[(eg * 4 + 0) * 264 + k];
            float2 a1 = *(const float2*)&s_big[(eg * 4 + 1) * 264 + k];
            float2 a2 = *(const float2*)&s_big[(eg * 4 + 2) * 264 + k];
            float2 a3 = *(const float2*)&s_big[(eg * 4 + 3) * 264 + k];
            ulonglong2 b0 = *(const ulonglong2*)(we2 + (k + 0) * 64 + cg * 4);
            ulonglong2 b1 = *(const ulonglong2*)(we2 + (k + 1) * 64 + cg * 4);
            ull p;
            p = pack2(a0.x); ffma2(acc01[0], p, b0.x); ffma2(acc23[0], p, b0.y);
            p = pack2(a1.x); ffma2(acc01[1], p, b0.x); ffma2(acc23[1], p, b0.y);
            p = pack2(a2.x); ffma2(acc01[2], p, b0.x); ffma2(acc23[2], p, b0.y);
            p = pack2(a3.x); ffma2(acc01[3], p, b0.x); ffma2(acc23[3], p, b0.y);
            p = pack2(a0.y); ffma2(acc01[0], p, b1.x); ffma2(acc23[0], p, b1.y);
            p = pack2(a1.y); ffma2(acc01[1], p, b1.x); ffma2(acc23[1], p, b1.y);
            p = pack2(a2.y); ffma2(acc01[2], p, b1.x); ffma2(acc23[2], p, b1.y);
            p = pack2(a3.y); ffma2(acc01[3], p, b1.x); ffma2(acc23[3], p, b1.y);
        }
        #pragma unroll
        for (int e = 0; e < 4; ++e) {
            float2 u0 = unpk(acc01[e]), u1 = unpk(acc23[e]);
            s_h2[eg * 4 + e][cg * 4 + 0] = fmaxf(u0.x + be2[cg * 4 + 0], 0.f);
            s_h2[eg * 4 + e][cg * 4 + 1] = fmaxf(u0.y + be2[cg * 4 + 1], 0.f);
            s_h2[eg * 4 + e][cg * 4 + 2] = fmaxf(u1.x + be2[cg * 4 + 2], 0.f);
            s_h2[eg * 4 + e][cg * 4 + 3] = fmaxf(u1.y + be2[cg * 4 + 3], 0.f);
        }
    }
    __syncthreads();

    // phase 3: L3 64->3 + sigmoid + priority bit
    if (t < 96) {
        int e = t / 3, c = t - (t / 3) * 3;
        float s = be3[c];
        #pragma unroll 8
        for (int k = 0; k < 64; ++k) s += s_h2[e][k] * we3[k * 3 + c];
        s_ea[e][c] = 1.f / (1.f + __expf(-s));
    }
    if (t < TE) s_ea[t][3] = (pri[s_src[t]] > pri[s_dst[t]]) ? 1.f : 0.f;
    __syncthreads();

    {
        int e = t >> 2, c = t & 3;
        if (e0 + e < NEDGE) out_ea[(size_t)(e0 + e) * 4 + c] = s_ea[e][c];
    }
}

// ---------------- message kernel: one block per src node ----------------
__global__ void __launch_bounds__(256) k_msg(
    const float* __restrict__ ea, const float* __restrict__ Mn,
    const float* __restrict__ cvec,
    const float* __restrict__ wp1, const float* __restrict__ bp1,
    float* __restrict__ out_agg) {
    __shared__ float sM[512];
    __shared__ float swp[512];
    __shared__ float sbp[128];
    const int src = blockIdx.x, t = threadIdx.x;
    sM[t] = Mn[src * 512 + t];
    sM[t + 256] = Mn[src * 512 + 256 + t];
    swp[t] = wp1[t]; swp[t + 256] = wp1[t + 256];
    if (t < 128) sbp[t] = bp1[t];
    __syncthreads();

    float4 cv = *(const float4*)(cvec + src * 4);
    const int slot = t >> 2, q = t & 3;
    for (int eb = 0; eb < 4; ++eb) {
        int el = eb * 64 + slot;
        if (el >= 199) break;
        int dst = el + (el >= src ? 1 : 0);
        int e = src * 199 + el;
        float4 eav = ((const float4*)ea)[e];
        float4 a = make_float4(0.f, 0.f, 0.f, 0.f);
        #pragma unroll 8
        for (int kk = 0; kk < 32; ++kk) {
            int k = kk * 4 + q;
            float h = sbp[k] + eav.x * swp[k] + eav.y * swp[128 + k]
                             + eav.z * swp[256 + k] + eav.w * swp[384 + k];
            h = fmaxf(h, 0.f);
            float4 m = ((const float4*)sM)[k];
            a.x += h * m.x; a.y += h * m.y; a.z += h * m.z; a.w += h * m.w;
        }
        #pragma unroll
        for (int s = 1; s < 4; s <<= 1) {
            a.x += __shfl_xor_sync(0xffffffffu, a.x, s);
            a.y += __shfl_xor_sync(0xffffffffu, a.y, s);
            a.z += __shfl_xor_sync(0xffffffffu, a.z, s);
            a.w += __shfl_xor_sync(0xffffffffu, a.w, s);
        }
        if (q == 0) {
            atomicAdd(&out_agg[dst * 4 + 0], a.x + cv.x);
            atomicAdd(&out_agg[dst * 4 + 1], a.y + cv.y);
            atomicAdd(&out_agg[dst * 4 + 2], a.z + cv.z);
            atomicAdd(&out_agg[dst * 4 + 3], a.w + cv.w);
        }
    }
}

// ---------------- launch ----------------
extern "C" void kernel_launch(void* const* d_in, const int* in_sizes, int n_in,
                              void* d_out, int out_size) {
    const float* roi  = (const float*)d_in[0];
    const float* bbox = (const float*)d_in[1];
    const float* dir  = (const float*)d_in[2];
    const float* pri  = (const float*)d_in[3];
    const float* w1  = (const float*)d_in[4];  const float* b1  = (const float*)d_in[5];
    const float* w2  = (const float*)d_in[6];  const float* b2  = (const float*)d_in[7];
    const float* w3  = (const float*)d_in[8];  const float* b3  = (const float*)d_in[9];
    const float* wi  = (const float*)d_in[10]; const float* bi  = (const float*)d_in[11];
    const float* we1 = (const float*)d_in[12]; const float* be1 = (const float*)d_in[13];
    const float* we2 = (const float*)d_in[14]; const float* be2 = (const float*)d_in[15];
    const float* we3 = (const float*)d_in[16]; const float* be3 = (const float*)d_in[17];
    const float* wp1 = (const float*)d_in[18]; const float* bp1 = (const float*)d_in[19];
    const float* wp2 = (const float*)d_in[20]; const float* bp2 = (const float*)d_in[21];
    const float* rw  = (const float*)d_in[22]; const float* rb  = (const float*)d_in[23];
    float* out = (float*)d_out;

    float* scr;
    cudaGetSymbolAddress((void**)&scr, g_scr);
    float* p_h1 = scr + OFF_H1;
    float* p_h2 = scr + OFF_H2;
    float* p_x  = scr + OFF_X;
    float* p_M  = scr + OFF_M;
    float* p_P  = scr + OFF_P;
    float* p_Q  = scr + OFF_Q;
    float* p_cv = scr + OFF_CV;

    static cudaStream_t s2 = nullptr;
    static cudaEvent_t evF = nullptr, ev2 = nullptr;
    if (!s2) {
        cudaStreamCreateWithFlags(&s2, cudaStreamNonBlocking);
        cudaEventCreateWithFlags(&evF, cudaEventDisableTiming);
        cudaEventCreateWithFlags(&ev2, cudaEventDisableTiming);
    }

    // fork edge branch immediately (doesn't touch zeroed scratch)
    cudaEventRecord(evF, 0);
    cudaStreamWaitEvent(s2, evF, 0);
    k_pq<<<dim3(2, NNODE), 128, 0, s2>>>(bbox, dir, we1, p_P, p_Q);
    k_edge_mlp<<<(NEDGE + TE - 1) / TE, 128, 0, s2>>>(p_P, p_Q, pri, be1,
                                                      we2, be2, we3, be3,
                                                      out + 1600);
    cudaEventRecord(ev2, s2);

    // main chain (stream 0)
    cudaMemsetAsync(scr, 0, ZERO_CNT * sizeof(float), 0);
    sgemm_sk<0,0><<<dim3(4, 7, 8), 256, 0, 0>>>(roi,  w1, b1, p_h1, NNODE, HD1, IMGF, 256);
    sgemm_sk<1,0><<<dim3(2, 7, 8), 256, 0, 0>>>(p_h1, w2, b2, p_h2, NNODE, HD2, HD1, 64);
    sgemm_sk<1,0><<<dim3(8, 7, 4), 256, 0, 0>>>(p_h2, w3, b3, p_x,  NNODE, NCH, HD2, 64);
    // M = x @ wp2^T-permuted, transpose fused into B load (TRB=1)
    sgemm_sk<0,1><<<dim3(4, 7, 8), 256, 0, 0>>>(p_x, wp2, (const float*)nullptr, p_M,
                                                NNODE, 512, NCH, 128);
    k_vec4b<<<NNODE, 256, 0, 0>>>(p_x, wi, bi, bp2, rw, rb, out + 800, p_cv, out);

    // join: message passing + scatter
    cudaStreamWaitEvent(0, ev2, 0);
    k_msg<<<NNODE, 256, 0, 0>>>(out + 1600, p_M, p_cv, wp1, bp1, out);
}